// round 12
// baseline (speedup 1.0000x reference)
#include <cuda_runtime.h>
#include <math.h>

#define THREADS 256
#define STAGES  4                        // power of 2: ring index is an AND
#define V       2                        // float4 chunks per thread per tile
#define DEPTH   3                        // tiles in flight (24 KB, same as R5)
#define CPT     (THREADS * V)            // 512 chunks (16B) per tile

__device__ __forceinline__ void cp_async16(void* smem_dst, const void* gsrc) {
    unsigned saddr = (unsigned)__cvta_generic_to_shared(smem_dst);
    asm volatile("cp.async.cg.shared.global [%0], [%1], 16;\n"
                 :: "r"(saddr), "l"(gsrc));
}
__device__ __forceinline__ void cp_async_commit() {
    asm volatile("cp.async.commit_group;\n" ::: "memory");
}
template<int N>
__device__ __forceinline__ void cp_async_wait() {
    asm volatile("cp.async.wait_group %0;\n" :: "n"(N) : "memory");
}

__global__ __launch_bounds__(THREADS)
void wrpl_row_kernel(const float* __restrict__ scores,
                     const int* __restrict__ targets,
                     float* __restrict__ out,
                     int B, int C)
{
    // Thread-private 16B slots -> no cross-thread smem sharing -> no barriers
    // in the streaming loop; cp.async.wait_group orders own write/read.
    __shared__ float4 buf[STAGES][V][THREADS];   // 32 KB

    const int row = blockIdx.x;
    const float* s = scores + (size_t)row * (size_t)C;
    const int t  = targets[row];
    const int td = threadIdx.x;

    const float gt  = __ldg(s + t);
    const float thr = gt - 1.0f;                 // hinge: l > 0 <=> x > gt-1
    const float gtb = nextafterf(gt, -__int_as_float(0x7f800000)); // x>gtb <=> x>=gt

    const int nChunks = C >> 2;                  // C % 4 == 0 (C = 32000)
    const int nFull   = nChunks / CPT;           // guard-free tiles
    const int nTiles  = (nChunks + CPT - 1) / CPT;
    const int tb      = t >> 2;                  // chunk index containing j == t

    const float4* s4 = reinterpret_cast<const float4*>(s);

    int   cnt_rank = 0;
    int   cnt_pos  = 0;
    float xsum     = 0.0f;

    // ---- prologue: DEPTH tiles in flight ----
    #pragma unroll
    for (int pt = 0; pt < DEPTH; ++pt) {
        #pragma unroll
        for (int k = 0; k < V; ++k) {
            int c4 = pt * CPT + k * THREADS + td;
            if (c4 < nChunks)
                cp_async16(&buf[pt][k][td], s4 + c4);
        }
        cp_async_commit();
    }

    // chunks <= tb counted with GE semantics (th = gtb), > tb with GT (th = gt)
#define PROC4(vv, thv)                                                          \
    { float x = (vv).x; cnt_rank += (x > (thv)); bool p = (x > thr); cnt_pos += p; if (p) xsum += x; } \
    { float x = (vv).y; cnt_rank += (x > (thv)); bool p = (x > thr); cnt_pos += p; if (p) xsum += x; } \
    { float x = (vv).z; cnt_rank += (x > (thv)); bool p = (x > thr); cnt_pos += p; if (p) xsum += x; } \
    { float x = (vv).w; cnt_rank += (x > (thv)); bool p = (x > thr); cnt_pos += p; if (p) xsum += x; }

    // ---- streaming loop: branch-free compare, barrier-free ----
    for (int tile = 0; tile < nTiles; ++tile) {
        const int it = tile + DEPTH;
        if (it < nTiles) {
            const int st = it & (STAGES - 1);
            #pragma unroll
            for (int k = 0; k < V; ++k) {
                int c4i = it * CPT + k * THREADS + td;
                if (c4i < nChunks)
                    cp_async16(&buf[st][k][td], s4 + c4i);
            }
        }
        cp_async_commit();
        cp_async_wait<DEPTH>();                  // own tile `tile` complete

        const int st = tile & (STAGES - 1);
        if (tile < nFull) {                      // guard-free hot path
            #pragma unroll
            for (int k = 0; k < V; ++k) {
                const int c4 = tile * CPT + k * THREADS + td;
                const float th = (c4 <= tb) ? gtb : gt;
                float4 v = buf[st][k][td];
                PROC4(v, th)
            }
        } else {                                 // tail tile
            #pragma unroll
            for (int k = 0; k < V; ++k) {
                const int c4 = tile * CPT + k * THREADS + td;
                if (c4 < nChunks) {
                    const float th = (c4 <= tb) ? gtb : gt;
                    float4 v = buf[st][k][td];
                    PROC4(v, th)
                }
            }
        }
    }
#undef PROC4

    // ---- exact correction for the boundary chunk (thread 0) ----
    //   idx == t          : rank -= 1, pos -= 1, xsum -= gt
    //   idx  > t, x == gt : rank -= 1  (counted under GE, should be GT)
    if (td == 0) {
        const int base = tb << 2;
        #pragma unroll
        for (int e = 0; e < 4; ++e) {
            const int idx = base + e;
            const float x = __ldg(s + idx);
            if (idx == t) {
                cnt_rank -= 1;
                cnt_pos  -= 1;
                xsum     -= gt;
            } else if (idx > t && x == gt) {
                cnt_rank -= 1;
            }
        }
    }

    // ---- block reduction ----
    const unsigned FULL = 0xFFFFFFFFu;
    #pragma unroll
    for (int off = 16; off > 0; off >>= 1) {
        cnt_rank += __shfl_down_sync(FULL, cnt_rank, off);
        cnt_pos  += __shfl_down_sync(FULL, cnt_pos,  off);
        xsum     += __shfl_down_sync(FULL, xsum,     off);
    }

    __shared__ int   sh_rk [THREADS / 32];
    __shared__ int   sh_pos[THREADS / 32];
    __shared__ float sh_xs [THREADS / 32];

    const int lane = td & 31;
    const int wid  = td >> 5;
    if (lane == 0) {
        sh_rk[wid]  = cnt_rank;
        sh_pos[wid] = cnt_pos;
        sh_xs[wid]  = xsum;
    }
    __syncthreads();

    if (td == 0) {
        int   rk = 0, p = 0;
        float xs = 0.0f;
        #pragma unroll
        for (int i = 0; i < THREADS / 32; i++) {
            rk += sh_rk[i]; p += sh_pos[i]; xs += sh_xs[i];
        }

        const int rank = rk + 1;
        const float hinge = xs - (float)p * thr;

        // harmonic number H(rank)
        double H;
        if (rank <= 64) {
            H = 0.0;
            for (int i = 1; i <= rank; i++) H += 1.0 / (double)i;
        } else {
            double n  = (double)rank;
            double n2 = n * n;
            H = log(n) + 0.57721566490153286
              + 1.0 / (2.0 * n) - 1.0 / (12.0 * n2) + 1.0 / (120.0 * n2 * n2);
        }

        float npos = (float)p + 1e-7f;
        float loss = (float)H / npos * hinge;
        atomicAdd(out, loss / (float)B);
    }
}

extern "C" void kernel_launch(void* const* d_in, const int* in_sizes, int n_in,
                              void* d_out, int out_size)
{
    const float* scores  = (const float*)d_in[0];
    const int*   targets = (const int*)d_in[1];
    float*       out     = (float*)d_out;

    const int B = in_sizes[1];
    const int C = in_sizes[0] / B;

    cudaMemsetAsync(out, 0, sizeof(float));
    wrpl_row_kernel<<<B, THREADS>>>(scores, targets, out, B, C);
}